// round 1
// baseline (speedup 1.0000x reference)
#include <cuda_runtime.h>
#include <cstdint>

#define HW   409600       // 640*640
#define HW4  102400       // HW/4
#define NCB  16           // 2 classes * 8 batch
#define NK   5            // kernel maps per class
#define EPSV 1e-4

struct Scratch {
    int      pos[NCB];
    int      negtot[NCB];
    int      fallback[NCB];
    unsigned bucket[NCB];
    int      rank2[NCB];
    float    thr[NCB];
    double   ta[NCB], tb_[NCB], tc_[NCB];
    double   ka[NCB][NK], kb[NCB][NK], kc[NCB][NK];
    int      hist1[NCB][65536];
    int      hist2[NCB][65536];
};
__device__ Scratch g;

__device__ __forceinline__ unsigned f2key(float f) {
    unsigned u = __float_as_uint(f);
    return (u & 0x80000000u) ? ~u : (u | 0x80000000u);
}
__device__ __forceinline__ float key2f(unsigned k) {
    unsigned u = (k & 0x80000000u) ? (k ^ 0x80000000u) : ~k;
    return __uint_as_float(u);
}
__device__ __forceinline__ float sigmoidf(float x) {
    return 1.0f / (1.0f + __expf(-x));
}
__device__ __forceinline__ float wredf(float v) {
    v += __shfl_down_sync(0xffffffffu, v, 16);
    v += __shfl_down_sync(0xffffffffu, v, 8);
    v += __shfl_down_sync(0xffffffffu, v, 4);
    v += __shfl_down_sync(0xffffffffu, v, 2);
    v += __shfl_down_sync(0xffffffffu, v, 1);
    return v;
}
__device__ __forceinline__ int wredi(int v) {
    v += __shfl_down_sync(0xffffffffu, v, 16);
    v += __shfl_down_sync(0xffffffffu, v, 8);
    v += __shfl_down_sync(0xffffffffu, v, 4);
    v += __shfl_down_sync(0xffffffffu, v, 2);
    v += __shfl_down_sync(0xffffffffu, v, 1);
    return v;
}

// Pass 1: reads everything once. Computes per-(c,b):
//   pos count, neg count, 16-bit histogram of neg text scores,
//   and the 5 kernel-channel dice partial sums (sel_k doesn't need OHEM).
__global__ void pass1(const float* __restrict__ outp, const float* __restrict__ lab,
                      const float* __restrict__ tmask) {
    int cb = blockIdx.y;
    int c = cb >> 3, b = cb & 7;
    const float4* tx = (const float4*)(outp + (size_t)(b * 12 + c * 6 + 5) * HW);
    const float4* gt = (const float4*)(lab  + (size_t)(b * 12 + c * 6 + 5) * HW);
    const float4* tm = (const float4*)(tmask + (size_t)b * HW);
    const float4* kv[NK];
    const float4* gk[NK];
#pragma unroll
    for (int k = 0; k < NK; k++) {
        kv[k] = (const float4*)(outp + (size_t)(b * 12 + c * 6 + k) * HW);
        gk[k] = (const float4*)(lab  + (size_t)(b * 12 + c * 6 + k) * HW);
    }

    float a_[NK], b_[NK], c_[NK];
#pragma unroll
    for (int k = 0; k < NK; k++) { a_[k] = 0.f; b_[k] = 0.f; c_[k] = 0.f; }
    int pos = 0, neg = 0;

    for (int i = blockIdx.x * blockDim.x + threadIdx.x; i < HW4;
         i += gridDim.x * blockDim.x) {
        float4 s4 = tx[i], g4 = gt[i], m4 = tm[i];
        float sv[4] = {s4.x, s4.y, s4.z, s4.w};
        float gv[4] = {g4.x, g4.y, g4.z, g4.w};
        float mv[4] = {m4.x, m4.y, m4.z, m4.w};
        float sel[4];
#pragma unroll
        for (int l = 0; l < 4; l++) {
            bool mp = mv[l] > 0.5f;
            bool gp = gv[l] > 0.5f;
            pos += (gp && mp) ? 1 : 0;
            if (!gp) {   // gt <= 0.5
                neg++;
                atomicAdd(&g.hist1[cb][f2key(sv[l]) >> 16], 1);
            }
            sel[l] = (sv[l] > 0.0f && mp) ? 1.0f : 0.0f;
        }
#pragma unroll
        for (int k = 0; k < NK; k++) {
            float4 p4 = kv[k][i], t4 = gk[k][i];
            float pv[4] = {p4.x, p4.y, p4.z, p4.w};
            float tv[4] = {t4.x, t4.y, t4.z, t4.w};
#pragma unroll
            for (int l = 0; l < 4; l++) {
                float p = sigmoidf(pv[l]) * sel[l];
                float t = tv[l] * sel[l];
                a_[k] = fmaf(p, t, a_[k]);
                b_[k] = fmaf(p, p, b_[k]);
                c_[k] = fmaf(t, t, c_[k]);
            }
        }
    }

    __shared__ double sacc[3 * NK];
    __shared__ int scnt[2];
    if (threadIdx.x < 3 * NK) sacc[threadIdx.x] = 0.0;
    if (threadIdx.x < 2) scnt[threadIdx.x] = 0;
    __syncthreads();
    int lane = threadIdx.x & 31;
#pragma unroll
    for (int k = 0; k < NK; k++) {
        float ra = wredf(a_[k]);
        float rb = wredf(b_[k]);
        float rc = wredf(c_[k]);
        if (lane == 0) {
            atomicAdd(&sacc[k], (double)ra);
            atomicAdd(&sacc[NK + k], (double)rb);
            atomicAdd(&sacc[2 * NK + k], (double)rc);
        }
    }
    int rp = wredi(pos), rn = wredi(neg);
    if (lane == 0) { atomicAdd(&scnt[0], rp); atomicAdd(&scnt[1], rn); }
    __syncthreads();
    if (threadIdx.x < NK)               atomicAdd(&g.ka[cb][threadIdx.x], sacc[threadIdx.x]);
    else if (threadIdx.x < 2 * NK)      atomicAdd(&g.kb[cb][threadIdx.x - NK], sacc[threadIdx.x]);
    else if (threadIdx.x < 3 * NK)      atomicAdd(&g.kc[cb][threadIdx.x - 2 * NK], sacc[threadIdx.x]);
    if (threadIdx.x == 16) atomicAdd(&g.pos[cb], scnt[0]);
    if (threadIdx.x == 17) atomicAdd(&g.negtot[cb], scnt[1]);
}

// Scan a 65536-bin histogram from the TOP bin down, find the bin containing
// the rank-th largest element. stage 1: hist1 -> bucket + residual rank.
// stage 2: hist2 -> exact float threshold.
__global__ void select_stage(int stage) {
    int cb = blockIdx.x;
    int rank;
    if (stage == 1) {
        int pos = g.pos[cb], ntot = g.negtot[cb];
        int nn = min(pos * 3, ntot);
        int fb = (pos == 0 || nn == 0) ? 1 : 0;
        if (threadIdx.x == 0) g.fallback[cb] = fb;
        if (fb) return;
        rank = nn;
    } else {
        if (g.fallback[cb]) return;
        rank = g.rank2[cb];
    }
    const int* hist = (stage == 1) ? g.hist1[cb] : g.hist2[cb];

    int t = threadIdx.x;                    // 1024 threads, 64 bins each
    int base = 65536 - 64 * (t + 1);        // thread 0 owns the top chunk
    int s = 0;
#pragma unroll 8
    for (int j = 0; j < 64; j++) s += hist[base + j];

    __shared__ int psum[1024];
    psum[t] = s;
    __syncthreads();
    // inclusive prefix over descending-bin chunk order (Hillis-Steele)
    for (int off = 1; off < 1024; off <<= 1) {
        int v = 0;
        if (t >= off) v = psum[t - off];
        __syncthreads();
        if (t >= off) psum[t] += v;
        __syncthreads();
    }
    int incl = psum[t];
    int excl = incl - s;
    if (rank > excl && rank <= incl) {
        int r = rank - excl;
        int cum = 0;
        for (int j = 63; j >= 0; j--) {
            int h = hist[base + j];
            cum += h;
            if (cum >= r) {
                if (stage == 1) {
                    g.bucket[cb] = (unsigned)(base + j);
                    g.rank2[cb]  = r - (cum - h);
                } else {
                    unsigned key = (g.bucket[cb] << 16) | (unsigned)(base + j);
                    g.thr[cb] = key2f(key);
                }
                break;
            }
        }
    }
}

// Refine: histogram of the low 16 key bits for neg pixels inside the chosen bucket.
__global__ void pass_refine(const float* __restrict__ outp, const float* __restrict__ lab) {
    int cb = blockIdx.y;
    if (g.fallback[cb]) return;
    unsigned buck = g.bucket[cb];
    int c = cb >> 3, b = cb & 7;
    const float4* tx = (const float4*)(outp + (size_t)(b * 12 + c * 6 + 5) * HW);
    const float4* gt = (const float4*)(lab  + (size_t)(b * 12 + c * 6 + 5) * HW);
    for (int i = blockIdx.x * blockDim.x + threadIdx.x; i < HW4;
         i += gridDim.x * blockDim.x) {
        float4 s4 = tx[i], g4 = gt[i];
        float sv[4] = {s4.x, s4.y, s4.z, s4.w};
        float gv[4] = {g4.x, g4.y, g4.z, g4.w};
#pragma unroll
        for (int l = 0; l < 4; l++) {
            if (gv[l] <= 0.5f) {
                unsigned k = f2key(sv[l]);
                if ((k >> 16) == buck) atomicAdd(&g.hist2[cb][k & 0xFFFFu], 1);
            }
        }
    }
}

// Text dice with the OHEM-selected mask (or raw tm on fallback).
__global__ void pass_text(const float* __restrict__ outp, const float* __restrict__ lab,
                          const float* __restrict__ tmask) {
    int cb = blockIdx.y;
    int c = cb >> 3, b = cb & 7;
    int fb = g.fallback[cb];
    float thr = g.thr[cb];
    const float4* tx = (const float4*)(outp + (size_t)(b * 12 + c * 6 + 5) * HW);
    const float4* gt = (const float4*)(lab  + (size_t)(b * 12 + c * 6 + 5) * HW);
    const float4* tm = (const float4*)(tmask + (size_t)b * HW);

    float ta = 0.f, tb = 0.f, tc = 0.f;
    for (int i = blockIdx.x * blockDim.x + threadIdx.x; i < HW4;
         i += gridDim.x * blockDim.x) {
        float4 s4 = tx[i], g4 = gt[i], m4 = tm[i];
        float sv[4] = {s4.x, s4.y, s4.z, s4.w};
        float gv[4] = {g4.x, g4.y, g4.z, g4.w};
        float mv[4] = {m4.x, m4.y, m4.z, m4.w};
#pragma unroll
        for (int l = 0; l < 4; l++) {
            float m;
            if (fb) m = mv[l];
            else    m = (((sv[l] >= thr) || (gv[l] > 0.5f)) && (mv[l] > 0.5f)) ? 1.0f : 0.0f;
            float p = sigmoidf(sv[l]) * m;
            float t = gv[l] * m;
            ta = fmaf(p, t, ta);
            tb = fmaf(p, p, tb);
            tc = fmaf(t, t, tc);
        }
    }

    __shared__ double sacc[3];
    if (threadIdx.x < 3) sacc[threadIdx.x] = 0.0;
    __syncthreads();
    int lane = threadIdx.x & 31;
    float ra = wredf(ta), rb = wredf(tb), rc = wredf(tc);
    if (lane == 0) {
        atomicAdd(&sacc[0], (double)ra);
        atomicAdd(&sacc[1], (double)rb);
        atomicAdd(&sacc[2], (double)rc);
    }
    __syncthreads();
    if (threadIdx.x == 0) atomicAdd(&g.ta[cb], sacc[0]);
    if (threadIdx.x == 1) atomicAdd(&g.tb_[cb], sacc[1]);
    if (threadIdx.x == 2) atomicAdd(&g.tc_[cb], sacc[2]);
}

__global__ void finalize(float* __restrict__ res) {
    if (threadIdx.x != 0) return;
    double loss_sum = 0.0, lt_sum = 0.0, lk_sum = 0.0;
    for (int c = 0; c < 2; c++) {
        double lt = 0.0, lk = 0.0;
        for (int b = 0; b < 8; b++) {
            int cb = c * 8 + b;
            lt += 1.0 - 2.0 * g.ta[cb] / (g.tb_[cb] + g.tc_[cb] + 2.0 * EPSV);
            double dks = 0.0;
            for (int k = 0; k < NK; k++)
                dks += 1.0 - 2.0 * g.ka[cb][k] / (g.kb[cb][k] + g.kc[cb][k] + 2.0 * EPSV);
            lk += dks / (double)NK;
        }
        lt /= 8.0;
        lk /= 8.0;
        lt_sum += lt;
        lk_sum += lk;
        loss_sum += 0.7 * lt + 0.3 * lk;
    }
    res[0] = (float)(loss_sum / 2.0);
    res[1] = (float)(lt_sum / 2.0);
    res[2] = (float)(lk_sum / 2.0);
}

extern "C" void kernel_launch(void* const* d_in, const int* in_sizes, int n_in,
                              void* d_out, int out_size) {
    const float* outp = (const float*)d_in[0];
    const float* lab  = (const float*)d_in[1];
    const float* tm   = (const float*)d_in[2];
    float* res = (float*)d_out;

    void* gaddr = nullptr;
    cudaGetSymbolAddress(&gaddr, g);
    cudaMemsetAsync(gaddr, 0, sizeof(Scratch));

    dim3 g1(100, 16);
    pass1<<<g1, 256>>>(outp, lab, tm);
    select_stage<<<16, 1024>>>(1);
    dim3 g2(50, 16);
    pass_refine<<<g2, 256>>>(outp, lab);
    select_stage<<<16, 1024>>>(2);
    pass_text<<<g2, 256>>>(outp, lab, tm);
    finalize<<<1, 32>>>(res);
}

// round 2
// speedup vs baseline: 1.4791x; 1.4791x over previous
#include <cuda_runtime.h>
#include <cstdint>
#include <cstddef>

#define HW   409600       // 640*640
#define HW4  102400       // HW/4
#define NCB  16           // 2 classes * 8 batch
#define NK   5            // kernel maps per class
#define EPSV 1e-4

// mode: 0 = FAST (nn==negtot, sel == tm>0.5), 1 = FALLBACK (mask = tm float),
//       2 = SLOW (need exact radix-select threshold)
struct Scratch {
    int      pos[NCB];
    int      negtot[NCB];
    unsigned maxinv[NCB];      // max of ~key over neg pixels (memset-0 identity)
    int      mode[NCB];
    int      nn[NCB];
    int      anyslow;
    unsigned bucket[NCB];
    int      rank2[NCB];
    float    thr[NCB];
    double   ta[NCB],  tb_[NCB], tc_[NCB];    // text dice, binary tm>0.5 mask
    double   taf[NCB], tbf[NCB], tcf[NCB];    // text dice, float tm mask (fallback)
    double   ta2[NCB], tb2[NCB], tc2[NCB];    // text dice, thr-based (slow path)
    double   ka[NCB][NK], kb[NCB][NK], kc[NCB][NK];
    int      hist1[NCB][65536];               // only touched on slow path
    int      hist2[NCB][65536];
};
__device__ Scratch g;

__device__ __forceinline__ unsigned f2key(float f) {
    unsigned u = __float_as_uint(f);
    return (u & 0x80000000u) ? ~u : (u | 0x80000000u);
}
__device__ __forceinline__ float key2f(unsigned k) {
    unsigned u = (k & 0x80000000u) ? (k ^ 0x80000000u) : ~k;
    return __uint_as_float(u);
}
__device__ __forceinline__ float sigmoidf(float x) {
    return 1.0f / (1.0f + __expf(-x));
}
__device__ __forceinline__ float wredf(float v) {
#pragma unroll
    for (int o = 16; o; o >>= 1) v += __shfl_down_sync(0xffffffffu, v, o);
    return v;
}
__device__ __forceinline__ int wredi(int v) {
#pragma unroll
    for (int o = 16; o; o >>= 1) v += __shfl_down_sync(0xffffffffu, v, o);
    return v;
}
__device__ __forceinline__ unsigned wredmaxu(unsigned v) {
#pragma unroll
    for (int o = 16; o; o >>= 1) v = max(v, __shfl_down_sync(0xffffffffu, v, o));
    return v;
}

// ---------------------------------------------------------------------------
// Pass 1: the ONLY full-data pass. Per (c,b):
//   pos/neg counts, max(~key) over neg text scores (=> min neg score),
//   kernel-channel dice sums (mask = texts>0 & tm>0.5, OHEM-independent),
//   speculative text dice sums for FAST mask (tm>0.5) and FALLBACK mask (tm).
// ---------------------------------------------------------------------------
__global__ void pass1(const float* __restrict__ outp, const float* __restrict__ lab,
                      const float* __restrict__ tmask) {
    int cb = blockIdx.y;
    int c = cb >> 3, b = cb & 7;
    const float4* ob = (const float4*)outp + (size_t)(b * 12 + c * 6) * HW4;
    const float4* lb = (const float4*)lab  + (size_t)(b * 12 + c * 6) * HW4;
    const float4* tm = (const float4*)tmask + (size_t)b * HW4;

    float ka_[NK], kb_[NK], kc_[NK];
#pragma unroll
    for (int k = 0; k < NK; k++) { ka_[k] = 0.f; kb_[k] = 0.f; kc_[k] = 0.f; }
    float tA = 0.f, tB = 0.f, tC = 0.f;      // binary mask
    float fA = 0.f, fB = 0.f, fC = 0.f;      // float tm mask
    int pos = 0, neg = 0;
    unsigned mxi = 0u;

    for (int i = blockIdx.x * blockDim.x + threadIdx.x; i < HW4;
         i += gridDim.x * blockDim.x) {
        float4 s4 = ob[5 * HW4 + i];
        float4 g4 = lb[5 * HW4 + i];
        float4 m4 = tm[i];
        float sv[4] = {s4.x, s4.y, s4.z, s4.w};
        float gv[4] = {g4.x, g4.y, g4.z, g4.w};
        float mv[4] = {m4.x, m4.y, m4.z, m4.w};
        float sel[4];
#pragma unroll
        for (int l = 0; l < 4; l++) {
            bool mp = mv[l] > 0.5f;
            bool gp = gv[l] > 0.5f;
            pos += (gp && mp) ? 1 : 0;
            if (!gp) { neg++; mxi = max(mxi, ~f2key(sv[l])); }
            float sg = sigmoidf(sv[l]);
            // FAST text mask (tm>0.5 binary)
            float mA = mp ? 1.0f : 0.0f;
            float pA = sg * mA, tAv = gv[l] * mA;
            tA = fmaf(pA, tAv, tA);
            tB = fmaf(pA, pA, tB);
            tC = fmaf(tAv, tAv, tC);
            // FALLBACK text mask (tm float)
            float pF = sg * mv[l], tFv = gv[l] * mv[l];
            fA = fmaf(pF, tFv, fA);
            fB = fmaf(pF, pF, fB);
            fC = fmaf(tFv, tFv, fC);
            sel[l] = (sv[l] > 0.0f && mp) ? 1.0f : 0.0f;
        }
#pragma unroll
        for (int k = 0; k < NK; k++) {
            float4 p4 = ob[k * HW4 + i];
            float4 t4 = lb[k * HW4 + i];
            float pv[4] = {p4.x, p4.y, p4.z, p4.w};
            float tv[4] = {t4.x, t4.y, t4.z, t4.w};
#pragma unroll
            for (int l = 0; l < 4; l++) {
                float p = sigmoidf(pv[l]) * sel[l];
                float t = tv[l] * sel[l];
                ka_[k] = fmaf(p, t, ka_[k]);
                kb_[k] = fmaf(p, p, kb_[k]);
                kc_[k] = fmaf(t, t, kc_[k]);
            }
        }
    }

    __shared__ double sacc[3 * NK + 6];
    __shared__ int scnt[2];
    __shared__ unsigned smx;
    if (threadIdx.x < 3 * NK + 6) sacc[threadIdx.x] = 0.0;
    if (threadIdx.x < 2) scnt[threadIdx.x] = 0;
    if (threadIdx.x == 2) smx = 0u;
    __syncthreads();
    int lane = threadIdx.x & 31;
#pragma unroll
    for (int k = 0; k < NK; k++) {
        float ra = wredf(ka_[k]), rb = wredf(kb_[k]), rc = wredf(kc_[k]);
        if (lane == 0) {
            atomicAdd(&sacc[k], (double)ra);
            atomicAdd(&sacc[NK + k], (double)rb);
            atomicAdd(&sacc[2 * NK + k], (double)rc);
        }
    }
    {
        float r0 = wredf(tA), r1 = wredf(tB), r2 = wredf(tC);
        float r3 = wredf(fA), r4 = wredf(fB), r5 = wredf(fC);
        if (lane == 0) {
            atomicAdd(&sacc[3 * NK + 0], (double)r0);
            atomicAdd(&sacc[3 * NK + 1], (double)r1);
            atomicAdd(&sacc[3 * NK + 2], (double)r2);
            atomicAdd(&sacc[3 * NK + 3], (double)r3);
            atomicAdd(&sacc[3 * NK + 4], (double)r4);
            atomicAdd(&sacc[3 * NK + 5], (double)r5);
        }
    }
    int rp = wredi(pos), rn = wredi(neg);
    unsigned rm = wredmaxu(mxi);
    if (lane == 0) {
        atomicAdd(&scnt[0], rp);
        atomicAdd(&scnt[1], rn);
        atomicMax(&smx, rm);
    }
    __syncthreads();
    int t = threadIdx.x;
    if (t < NK)                atomicAdd(&g.ka[cb][t],          sacc[t]);
    else if (t < 2 * NK)       atomicAdd(&g.kb[cb][t - NK],     sacc[t]);
    else if (t < 3 * NK)       atomicAdd(&g.kc[cb][t - 2 * NK], sacc[t]);
    else if (t == 3 * NK + 0)  atomicAdd(&g.ta[cb],  sacc[t]);
    else if (t == 3 * NK + 1)  atomicAdd(&g.tb_[cb], sacc[t]);
    else if (t == 3 * NK + 2)  atomicAdd(&g.tc_[cb], sacc[t]);
    else if (t == 3 * NK + 3)  atomicAdd(&g.taf[cb], sacc[t]);
    else if (t == 3 * NK + 4)  atomicAdd(&g.tbf[cb], sacc[t]);
    else if (t == 3 * NK + 5)  atomicAdd(&g.tcf[cb], sacc[t]);
    else if (t == 3 * NK + 6)  atomicAdd(&g.pos[cb], scnt[0]);
    else if (t == 3 * NK + 7)  atomicAdd(&g.negtot[cb], scnt[1]);
    else if (t == 3 * NK + 8)  atomicMax(&g.maxinv[cb], smx);
}

// ---------------------------------------------------------------------------
// Decide per (c,b) which path applies.
// ---------------------------------------------------------------------------
__global__ void decide() {
    int t = threadIdx.x;
    if (t >= NCB) return;
    int pos = g.pos[t], ntot = g.negtot[t];
    int nn = min(pos * 3, ntot);
    int mode;
    if (pos == 0 || nn == 0)   mode = 1;       // fallback: mask = tm
    else if (nn == ntot)       mode = 0;       // thr = min neg => sel == tm>0.5
    else                       mode = 2;       // needs exact select
    g.mode[t] = mode;
    g.nn[t] = nn;
    if (mode == 2) atomicOr(&g.anyslow, 1);
}

// ---------- Slow path (general correctness; early-exits on this data) ------
__global__ void clear_hists() {
    if (!g.anyslow) return;
    int4* p = (int4*)g.hist1;                         // hist1+hist2 contiguous
    int n = (NCB * 65536 * 2) / 4;
    int4 z = {0, 0, 0, 0};
    for (int i = blockIdx.x * blockDim.x + threadIdx.x; i < n;
         i += gridDim.x * blockDim.x) p[i] = z;
}

__global__ void hist1_pass(const float* __restrict__ outp, const float* __restrict__ lab) {
    int cb = blockIdx.y;
    if (g.mode[cb] != 2) return;
    int c = cb >> 3, b = cb & 7;
    const float4* tx = (const float4*)outp + (size_t)(b * 12 + c * 6 + 5) * HW4;
    const float4* gt = (const float4*)lab  + (size_t)(b * 12 + c * 6 + 5) * HW4;
    for (int i = blockIdx.x * blockDim.x + threadIdx.x; i < HW4;
         i += gridDim.x * blockDim.x) {
        float4 s4 = tx[i], g4 = gt[i];
        float sv[4] = {s4.x, s4.y, s4.z, s4.w};
        float gv[4] = {g4.x, g4.y, g4.z, g4.w};
#pragma unroll
        for (int l = 0; l < 4; l++)
            if (gv[l] <= 0.5f) atomicAdd(&g.hist1[cb][f2key(sv[l]) >> 16], 1);
    }
}

__global__ void select_stage(int stage) {
    int cb = blockIdx.x;
    if (g.mode[cb] != 2) return;
    int rank = (stage == 1) ? g.nn[cb] : g.rank2[cb];
    const int* hist = (stage == 1) ? g.hist1[cb] : g.hist2[cb];

    int t = threadIdx.x;                    // 1024 threads, 64 bins each
    int base = 65536 - 64 * (t + 1);        // thread 0 owns the top chunk
    const int4* h4 = (const int4*)(hist + base);
    int s = 0;
#pragma unroll
    for (int j = 0; j < 16; j++) {
        int4 v = h4[j];
        s += v.x + v.y + v.z + v.w;
    }
    __shared__ int psum[1024];
    psum[t] = s;
    __syncthreads();
    for (int off = 1; off < 1024; off <<= 1) {
        int v = 0;
        if (t >= off) v = psum[t - off];
        __syncthreads();
        if (t >= off) psum[t] += v;
        __syncthreads();
    }
    int incl = psum[t], excl = incl - s;
    if (rank > excl && rank <= incl) {
        int r = rank - excl, cum = 0;
        for (int j = 63; j >= 0; j--) {
            int h = hist[base + j];
            cum += h;
            if (cum >= r) {
                if (stage == 1) {
                    g.bucket[cb] = (unsigned)(base + j);
                    g.rank2[cb]  = r - (cum - h);
                } else {
                    unsigned key = (g.bucket[cb] << 16) | (unsigned)(base + j);
                    g.thr[cb] = key2f(key);
                }
                break;
            }
        }
    }
}

__global__ void pass_refine(const float* __restrict__ outp, const float* __restrict__ lab) {
    int cb = blockIdx.y;
    if (g.mode[cb] != 2) return;
    unsigned buck = g.bucket[cb];
    int c = cb >> 3, b = cb & 7;
    const float4* tx = (const float4*)outp + (size_t)(b * 12 + c * 6 + 5) * HW4;
    const float4* gt = (const float4*)lab  + (size_t)(b * 12 + c * 6 + 5) * HW4;
    for (int i = blockIdx.x * blockDim.x + threadIdx.x; i < HW4;
         i += gridDim.x * blockDim.x) {
        float4 s4 = tx[i], g4 = gt[i];
        float sv[4] = {s4.x, s4.y, s4.z, s4.w};
        float gv[4] = {g4.x, g4.y, g4.z, g4.w};
#pragma unroll
        for (int l = 0; l < 4; l++) {
            if (gv[l] <= 0.5f) {
                unsigned k = f2key(sv[l]);
                if ((k >> 16) == buck) atomicAdd(&g.hist2[cb][k & 0xFFFFu], 1);
            }
        }
    }
}

__global__ void text_fix(const float* __restrict__ outp, const float* __restrict__ lab,
                         const float* __restrict__ tmask) {
    int cb = blockIdx.y;
    if (g.mode[cb] != 2) return;
    float thr = g.thr[cb];
    int c = cb >> 3, b = cb & 7;
    const float4* tx = (const float4*)outp + (size_t)(b * 12 + c * 6 + 5) * HW4;
    const float4* gt = (const float4*)lab  + (size_t)(b * 12 + c * 6 + 5) * HW4;
    const float4* tm = (const float4*)tmask + (size_t)b * HW4;

    float ta = 0.f, tb = 0.f, tc = 0.f;
    for (int i = blockIdx.x * blockDim.x + threadIdx.x; i < HW4;
         i += gridDim.x * blockDim.x) {
        float4 s4 = tx[i], g4 = gt[i], m4 = tm[i];
        float sv[4] = {s4.x, s4.y, s4.z, s4.w};
        float gv[4] = {g4.x, g4.y, g4.z, g4.w};
        float mv[4] = {m4.x, m4.y, m4.z, m4.w};
#pragma unroll
        for (int l = 0; l < 4; l++) {
            float m = (((sv[l] >= thr) || (gv[l] > 0.5f)) && (mv[l] > 0.5f)) ? 1.0f : 0.0f;
            float p = sigmoidf(sv[l]) * m;
            float t = gv[l] * m;
            ta = fmaf(p, t, ta);
            tb = fmaf(p, p, tb);
            tc = fmaf(t, t, tc);
        }
    }
    __shared__ double sacc[3];
    if (threadIdx.x < 3) sacc[threadIdx.x] = 0.0;
    __syncthreads();
    int lane = threadIdx.x & 31;
    float ra = wredf(ta), rb = wredf(tb), rc = wredf(tc);
    if (lane == 0) {
        atomicAdd(&sacc[0], (double)ra);
        atomicAdd(&sacc[1], (double)rb);
        atomicAdd(&sacc[2], (double)rc);
    }
    __syncthreads();
    if (threadIdx.x == 0) atomicAdd(&g.ta2[cb], sacc[0]);
    if (threadIdx.x == 1) atomicAdd(&g.tb2[cb], sacc[1]);
    if (threadIdx.x == 2) atomicAdd(&g.tc2[cb], sacc[2]);
}

__global__ void finalize(float* __restrict__ res) {
    if (threadIdx.x != 0) return;
    double loss_sum = 0.0, lt_sum = 0.0, lk_sum = 0.0;
    for (int c = 0; c < 2; c++) {
        double lt = 0.0, lk = 0.0;
        for (int b = 0; b < 8; b++) {
            int cb = c * 8 + b;
            double A, B, C;
            int m = g.mode[cb];
            if (m == 0)      { A = g.ta[cb];  B = g.tb_[cb]; C = g.tc_[cb]; }
            else if (m == 1) { A = g.taf[cb]; B = g.tbf[cb]; C = g.tcf[cb]; }
            else             { A = g.ta2[cb]; B = g.tb2[cb]; C = g.tc2[cb]; }
            lt += 1.0 - 2.0 * A / (B + C + 2.0 * EPSV);
            double dks = 0.0;
            for (int k = 0; k < NK; k++)
                dks += 1.0 - 2.0 * g.ka[cb][k] / (g.kb[cb][k] + g.kc[cb][k] + 2.0 * EPSV);
            lk += dks / (double)NK;
        }
        lt /= 8.0; lk /= 8.0;
        lt_sum += lt; lk_sum += lk;
        loss_sum += 0.7 * lt + 0.3 * lk;
    }
    res[0] = (float)(loss_sum / 2.0);
    res[1] = (float)(lt_sum / 2.0);
    res[2] = (float)(lk_sum / 2.0);
}

extern "C" void kernel_launch(void* const* d_in, const int* in_sizes, int n_in,
                              void* d_out, int out_size) {
    const float* outp = (const float*)d_in[0];
    const float* lab  = (const float*)d_in[1];
    const float* tm   = (const float*)d_in[2];
    float* res = (float*)d_out;

    void* gaddr = nullptr;
    cudaGetSymbolAddress(&gaddr, g);
    cudaMemsetAsync(gaddr, 0, offsetof(Scratch, hist1));   // header only, ~6 KB

    dim3 g1(100, 16);
    pass1<<<g1, 256>>>(outp, lab, tm);
    decide<<<1, 32>>>();
    // General-correctness machinery; all early-exit unless a SLOW cb exists.
    clear_hists<<<512, 256>>>();
    dim3 g2(50, 16);
    hist1_pass<<<g2, 256>>>(outp, lab);
    select_stage<<<16, 1024>>>(1);
    pass_refine<<<g2, 256>>>(outp, lab);
    select_stage<<<16, 1024>>>(2);
    text_fix<<<g2, 256>>>(outp, lab, tm);
    finalize<<<1, 32>>>(res);
}

// round 5
// speedup vs baseline: 2.1186x; 1.4324x over previous
#include <cuda_runtime.h>
#include <cstdint>
#include <cstddef>

#define HW   409600       // 640*640
#define HW4  102400       // HW/4
#define HWW  12800        // HW/32 sel words per cb
#define NCB  16           // 2 classes * 8 batch
#define NK   5            // kernel maps per class
#define EPSV 1e-4

// mode: 0 = FAST (nn==negtot => sel == tm>0.5), 1 = FALLBACK (mask = tm float),
//       2 = SLOW (exact radix-select threshold)
struct Scratch {
    int      pos[NCB];
    int      negtot[NCB];
    int      mode[NCB];
    float    thr[NCB];
    double   ta[NCB],  tb_[NCB], tc_[NCB];    // text dice, binary tm>0.5 mask
    double   taf[NCB], tbf[NCB], tcf[NCB];    // text dice, float tm (fallback)
    double   ta2[NCB], tb2[NCB], tc2[NCB];    // text dice, thr-based (slow)
    double   ka[NCB][NK], kb[NCB][NK], kc[NCB][NK];
    unsigned selw[NCB][HWW];                  // NOT memset; fully overwritten
};
__device__ Scratch g;

__device__ __forceinline__ unsigned f2key(float f) {
    unsigned u = __float_as_uint(f);
    return (u & 0x80000000u) ? ~u : (u | 0x80000000u);
}
__device__ __forceinline__ float key2f(unsigned k) {
    unsigned u = (k & 0x80000000u) ? (k ^ 0x80000000u) : ~k;
    return __uint_as_float(u);
}
__device__ __forceinline__ float sigmoidf(float x) {
    return 1.0f / (1.0f + __expf(-x));
}
__device__ __forceinline__ float wredf(float v) {
#pragma unroll
    for (int o = 16; o; o >>= 1) v += __shfl_down_sync(0xffffffffu, v, o);
    return v;
}
__device__ __forceinline__ int wredi(int v) {
#pragma unroll
    for (int o = 16; o; o >>= 1) v += __shfl_down_sync(0xffffffffu, v, o);
    return v;
}

// ---------------------------------------------------------------------------
// text_pass: texts + gt_texts + tm for each (c,b).
//   -> pos/neg counts, FAST text dice sums (mask = tm>0.5),
//      packed sel bits (texts>0 & tm>0.5) for the kernel-channel pass.
// grid (100, 16) x 256 threads: exactly 4 iterations per thread.
// ---------------------------------------------------------------------------
__global__ void __launch_bounds__(256) text_pass(
    const float* __restrict__ outp, const float* __restrict__ lab,
    const float* __restrict__ tmask) {
    int cb = blockIdx.y;
    int c = cb >> 3, b = cb & 7;
    const float4* tx = (const float4*)outp + (size_t)(b * 12 + c * 6 + 5) * HW4;
    const float4* gt = (const float4*)lab  + (size_t)(b * 12 + c * 6 + 5) * HW4;
    const float4* tm = (const float4*)tmask + (size_t)b * HW4;
    unsigned* selw = g.selw[cb];

    int base = blockIdx.x * 256 + threadIdx.x;   // stride 25600, 4 trips
    float tA = 0.f, tB = 0.f, tC = 0.f;
    int pos = 0, neg = 0;

#pragma unroll
    for (int it = 0; it < 4; it++) {
        int i = base + it * 25600;
        float4 s4 = tx[i], g4 = gt[i], m4 = tm[i];
        float sv[4] = {s4.x, s4.y, s4.z, s4.w};
        float gv[4] = {g4.x, g4.y, g4.z, g4.w};
        float mv[4] = {m4.x, m4.y, m4.z, m4.w};
        unsigned nib = 0;
#pragma unroll
        for (int l = 0; l < 4; l++) {
            bool mp = mv[l] > 0.5f;
            bool gp = gv[l] > 0.5f;
            pos += (gp && mp) ? 1 : 0;
            neg += gp ? 0 : 1;
            nib |= (sv[l] > 0.0f && mp) ? (1u << l) : 0u;
            float m = mp ? 1.0f : 0.0f;
            float p = sigmoidf(sv[l]) * m;
            float t = gv[l] * m;
            tA = fmaf(p, t, tA);
            tB = fmaf(p, p, tB);
            tC = fmaf(t, t, tC);
        }
        // assemble 8 nibbles (8 consecutive float4 lanes = 32 px) into one word
        unsigned v = nib << ((i & 7) * 4);
        v |= __shfl_xor_sync(0xffffffffu, v, 1);
        v |= __shfl_xor_sync(0xffffffffu, v, 2);
        v |= __shfl_xor_sync(0xffffffffu, v, 4);
        if ((i & 7) == 0) selw[i >> 3] = v;
    }

    __shared__ double sacc[3];
    __shared__ int scnt[2];
    if (threadIdx.x < 3) sacc[threadIdx.x] = 0.0;
    if (threadIdx.x < 2) scnt[threadIdx.x] = 0;
    __syncthreads();
    int lane = threadIdx.x & 31;
    float ra = wredf(tA), rb = wredf(tB), rc = wredf(tC);
    int rp = wredi(pos), rn = wredi(neg);
    if (lane == 0) {
        atomicAdd(&sacc[0], (double)ra);
        atomicAdd(&sacc[1], (double)rb);
        atomicAdd(&sacc[2], (double)rc);
        atomicAdd(&scnt[0], rp);
        atomicAdd(&scnt[1], rn);
    }
    __syncthreads();
    if (threadIdx.x == 0) atomicAdd(&g.ta[cb],  sacc[0]);
    if (threadIdx.x == 1) atomicAdd(&g.tb_[cb], sacc[1]);
    if (threadIdx.x == 2) atomicAdd(&g.tc_[cb], sacc[2]);
    if (threadIdx.x == 3) atomicAdd(&g.pos[cb], scnt[0]);
    if (threadIdx.x == 4) atomicAdd(&g.negtot[cb], scnt[1]);
}

// ---------------------------------------------------------------------------
// kern_pass: one (cb, k) channel pair per blockIdx.y (80 slices).
// Pure 2-stream read + broadcast sel word. grid (40, 80) x 256: 10 trips.
// ---------------------------------------------------------------------------
__global__ void __launch_bounds__(256) kern_pass(
    const float* __restrict__ outp, const float* __restrict__ lab) {
    int slice = blockIdx.y;
    int cb = slice / NK, k = slice % NK;
    int c = cb >> 3, b = cb & 7;
    const float4* pv4 = (const float4*)outp + (size_t)(b * 12 + c * 6 + k) * HW4;
    const float4* tv4 = (const float4*)lab  + (size_t)(b * 12 + c * 6 + k) * HW4;
    const unsigned* selw = g.selw[cb];

    int base = blockIdx.x * 256 + threadIdx.x;   // stride 10240, 10 trips
    float A = 0.f, B = 0.f, C = 0.f;

#pragma unroll 5
    for (int it = 0; it < 10; it++) {
        int i = base + it * 10240;
        float4 p4 = pv4[i];
        float4 t4 = tv4[i];
        unsigned w = selw[i >> 3];
        unsigned nib = (w >> ((i & 7) * 4)) & 0xFu;
        float pv[4] = {p4.x, p4.y, p4.z, p4.w};
        float tv[4] = {t4.x, t4.y, t4.z, t4.w};
#pragma unroll
        for (int l = 0; l < 4; l++) {
            bool s = (nib >> l) & 1u;
            float p = s ? sigmoidf(pv[l]) : 0.0f;
            float t = s ? tv[l] : 0.0f;
            A = fmaf(p, t, A);
            B = fmaf(p, p, B);
            C = fmaf(t, t, C);
        }
    }

    __shared__ double sacc[3];
    if (threadIdx.x < 3) sacc[threadIdx.x] = 0.0;
    __syncthreads();
    int lane = threadIdx.x & 31;
    float ra = wredf(A), rb = wredf(B), rc = wredf(C);
    if (lane == 0) {
        atomicAdd(&sacc[0], (double)ra);
        atomicAdd(&sacc[1], (double)rb);
        atomicAdd(&sacc[2], (double)rc);
    }
    __syncthreads();
    if (threadIdx.x == 0) atomicAdd(&g.ka[cb][k], sacc[0]);
    if (threadIdx.x == 1) atomicAdd(&g.kb[cb][k], sacc[1]);
    if (threadIdx.x == 2) atomicAdd(&g.kc[cb][k], sacc[2]);
}

// ---------------------------------------------------------------------------
// slow_path: ONE launch, 16 blocks (one per cb), 1024 threads.
// Computes mode; mode 0 exits. mode 1: float-tm text sums. mode 2: exact
// 4-round 8-bit radix select in SMEM, then thr-masked text sums.
// Only runs real work when the data demands it (never on this distribution).
// ---------------------------------------------------------------------------
__global__ void __launch_bounds__(1024) slow_path(
    const float* __restrict__ outp, const float* __restrict__ lab,
    const float* __restrict__ tmask) {
    int cb = blockIdx.x;
    int tid = threadIdx.x;
    int pos = g.pos[cb], ntot = g.negtot[cb];
    int nn = min(pos * 3, ntot);
    int mode = (pos == 0 || nn == 0) ? 1 : (nn == ntot ? 0 : 2);
    if (tid == 0) g.mode[cb] = mode;
    if (mode == 0) return;

    int c = cb >> 3, b = cb & 7;
    const float4* tx = (const float4*)outp + (size_t)(b * 12 + c * 6 + 5) * HW4;
    const float4* gt = (const float4*)lab  + (size_t)(b * 12 + c * 6 + 5) * HW4;
    const float4* tm = (const float4*)tmask + (size_t)b * HW4;

    __shared__ int shist[256];
    __shared__ int sd, srank;
    __shared__ double swarp[32][3];

    float thr = 0.0f;
    if (mode == 2) {
        // exact rank-nn largest among neg scores, 8 bits per round
        unsigned prefix = 0;
        int rank = nn;
        for (int r = 0; r < 4; r++) {
            int shift = 24 - 8 * r;
            for (int j = tid; j < 256; j += 1024) shist[j] = 0;
            __syncthreads();
            for (int i = tid; i < HW4; i += 1024) {
                float4 s4 = tx[i], g4 = gt[i];
                float sv[4] = {s4.x, s4.y, s4.z, s4.w};
                float gv[4] = {g4.x, g4.y, g4.z, g4.w};
#pragma unroll
                for (int l = 0; l < 4; l++) {
                    if (gv[l] <= 0.5f) {
                        unsigned key = f2key(sv[l]);
                        if (r == 0 || (key >> (shift + 8)) == prefix)
                            atomicAdd(&shist[(key >> shift) & 0xFF], 1);
                    }
                }
            }
            __syncthreads();
            if (tid == 0) {
                int cum = 0, d = 0, rnew = rank;
                for (int j = 255; j >= 0; j--) {
                    cum += shist[j];
                    if (cum >= rank) { d = j; rnew = rank - (cum - shist[j]); break; }
                }
                sd = d; srank = rnew;
            }
            __syncthreads();
            prefix = (prefix << 8) | (unsigned)sd;
            rank = srank;
            __syncthreads();
        }
        thr = key2f(prefix);
        if (tid == 0) g.thr[cb] = thr;
    }

    // text dice sums with the applicable mask
    float A = 0.f, B = 0.f, C = 0.f;
    for (int i = tid; i < HW4; i += 1024) {
        float4 s4 = tx[i], g4 = gt[i], m4 = tm[i];
        float sv[4] = {s4.x, s4.y, s4.z, s4.w};
        float gv[4] = {g4.x, g4.y, g4.z, g4.w};
        float mv[4] = {m4.x, m4.y, m4.z, m4.w};
#pragma unroll
        for (int l = 0; l < 4; l++) {
            float m;
            if (mode == 1) m = mv[l];
            else m = (((sv[l] >= thr) || (gv[l] > 0.5f)) && (mv[l] > 0.5f)) ? 1.0f : 0.0f;
            float p = sigmoidf(sv[l]) * m;
            float t = gv[l] * m;
            A = fmaf(p, t, A);
            B = fmaf(p, p, B);
            C = fmaf(t, t, C);
        }
    }
    int lane = tid & 31, wid = tid >> 5;
    float ra = wredf(A), rb = wredf(B), rc = wredf(C);
    if (lane == 0) { swarp[wid][0] = ra; swarp[wid][1] = rb; swarp[wid][2] = rc; }
    __syncthreads();
    if (tid == 0) {
        double a = 0, bb = 0, cc = 0;
        for (int w = 0; w < 32; w++) { a += swarp[w][0]; bb += swarp[w][1]; cc += swarp[w][2]; }
        if (mode == 1) { g.taf[cb] = a; g.tbf[cb] = bb; g.tcf[cb] = cc; }
        else           { g.ta2[cb] = a; g.tb2[cb] = bb; g.tc2[cb] = cc; }
    }
}

__global__ void finalize(float* __restrict__ res) {
    if (threadIdx.x != 0) return;
    double loss_sum = 0.0, lt_sum = 0.0, lk_sum = 0.0;
    for (int c = 0; c < 2; c++) {
        double lt = 0.0, lk = 0.0;
        for (int b = 0; b < 8; b++) {
            int cb = c * 8 + b;
            double A, B, C;
            int m = g.mode[cb];
            if (m == 0)      { A = g.ta[cb];  B = g.tb_[cb]; C = g.tc_[cb]; }
            else if (m == 1) { A = g.taf[cb]; B = g.tbf[cb]; C = g.tcf[cb]; }
            else             { A = g.ta2[cb]; B = g.tb2[cb]; C = g.tc2[cb]; }
            lt += 1.0 - 2.0 * A / (B + C + 2.0 * EPSV);
            double dks = 0.0;
            for (int k = 0; k < NK; k++)
                dks += 1.0 - 2.0 * g.ka[cb][k] / (g.kb[cb][k] + g.kc[cb][k] + 2.0 * EPSV);
            lk += dks / (double)NK;
        }
        lt /= 8.0; lk /= 8.0;
        lt_sum += lt; lk_sum += lk;
        loss_sum += 0.7 * lt + 0.3 * lk;
    }
    res[0] = (float)(loss_sum / 2.0);
    res[1] = (float)(lt_sum / 2.0);
    res[2] = (float)(lk_sum / 2.0);
}

extern "C" void kernel_launch(void* const* d_in, const int* in_sizes, int n_in,
                              void* d_out, int out_size) {
    const float* outp = (const float*)d_in[0];
    const float* lab  = (const float*)d_in[1];
    const float* tm   = (const float*)d_in[2];
    float* res = (float*)d_out;

    void* gaddr = nullptr;
    cudaGetSymbolAddress(&gaddr, g);
    cudaMemsetAsync(gaddr, 0, offsetof(Scratch, selw));   // ~3.4 KB header

    dim3 gt(100, 16);
    text_pass<<<gt, 256>>>(outp, lab, tm);
    dim3 gk(40, 80);
    kern_pass<<<gk, 256>>>(outp, lab);
    slow_path<<<16, 1024>>>(outp, lab, tm);
    finalize<<<1, 32>>>(res);
}

// round 7
// speedup vs baseline: 3.5573x; 1.6791x over previous
#include <cuda_runtime.h>
#include <cstdint>
#include <cstddef>

#define HW   409600       // 640*640
#define HW4  102400       // HW/4
#define HWW  12800        // HW/32 sel words per cb
#define NCB  16           // 2 classes * 8 batch
#define NK   5            // kernel maps per class
#define EPSV 1e-4

// mode: 0 = FAST (nn==negtot => sel == tm>0.5), 1 = FALLBACK (mask = tm float),
//       2 = SLOW (exact radix-select threshold)
struct Scratch {
    int      pos[NCB];
    int      negtot[NCB];
    int      mode[NCB];
    float    thr[NCB];
    double   ta[NCB],  tb_[NCB], tc_[NCB];    // text dice, binary tm>0.5 mask
    double   taf[NCB], tbf[NCB], tcf[NCB];    // text dice, float tm (fallback)
    double   ta2[NCB], tb2[NCB], tc2[NCB];    // text dice, thr-based (slow)
    double   ka[NCB][NK], kb[NCB][NK], kc[NCB][NK];
    unsigned selw[NCB][HWW];                  // NOT memset; fully overwritten
};
__device__ Scratch g;

__device__ __forceinline__ unsigned f2key(float f) {
    unsigned u = __float_as_uint(f);
    return (u & 0x80000000u) ? ~u : (u | 0x80000000u);
}
__device__ __forceinline__ float key2f(unsigned k) {
    unsigned u = (k & 0x80000000u) ? (k ^ 0x80000000u) : ~k;
    return __uint_as_float(u);
}
__device__ __forceinline__ float sigmoidf(float x) {
    return 1.0f / (1.0f + __expf(-x));
}
__device__ __forceinline__ float wredf(float v) {
#pragma unroll
    for (int o = 16; o; o >>= 1) v += __shfl_down_sync(0xffffffffu, v, o);
    return v;
}
__device__ __forceinline__ int wredi(int v) {
#pragma unroll
    for (int o = 16; o; o >>= 1) v += __shfl_down_sync(0xffffffffu, v, o);
    return v;
}

// ---------------------------------------------------------------------------
// text_pass: texts + gt_texts + tm for each (c,b).
//   -> pos/neg counts, FAST text dice sums (mask = tm>0.5),
//      packed sel bits (texts>0 & tm>0.5) for the kernel-channel pass.
// grid (100, 16) x 256 threads: exactly 4 iterations per thread.
// ---------------------------------------------------------------------------
__global__ void __launch_bounds__(256) text_pass(
    const float* __restrict__ outp, const float* __restrict__ lab,
    const float* __restrict__ tmask) {
    int cb = blockIdx.y;
    int c = cb >> 3, b = cb & 7;
    const float4* tx = (const float4*)outp + (size_t)(b * 12 + c * 6 + 5) * HW4;
    const float4* gt = (const float4*)lab  + (size_t)(b * 12 + c * 6 + 5) * HW4;
    const float4* tm = (const float4*)tmask + (size_t)b * HW4;
    unsigned* selw = g.selw[cb];

    int base = blockIdx.x * 256 + threadIdx.x;   // stride 25600, 4 trips
    float tA = 0.f, tB = 0.f, tC = 0.f;
    int pos = 0, neg = 0;

#pragma unroll
    for (int it = 0; it < 4; it++) {
        int i = base + it * 25600;
        float4 s4 = tx[i], g4 = gt[i], m4 = tm[i];
        float sv[4] = {s4.x, s4.y, s4.z, s4.w};
        float gv[4] = {g4.x, g4.y, g4.z, g4.w};
        float mv[4] = {m4.x, m4.y, m4.z, m4.w};
        unsigned nib = 0;
#pragma unroll
        for (int l = 0; l < 4; l++) {
            bool mp = mv[l] > 0.5f;
            bool gp = gv[l] > 0.5f;
            pos += (gp && mp) ? 1 : 0;
            neg += gp ? 0 : 1;
            nib |= (sv[l] > 0.0f && mp) ? (1u << l) : 0u;
            float m = mp ? 1.0f : 0.0f;
            float p = sigmoidf(sv[l]) * m;
            float t = gv[l] * m;
            tA = fmaf(p, t, tA);
            tB = fmaf(p, p, tB);
            tC = fmaf(t, t, tC);
        }
        // assemble 8 nibbles (8 consecutive float4 lanes = 32 px) into one word
        unsigned v = nib << ((i & 7) * 4);
        v |= __shfl_xor_sync(0xffffffffu, v, 1);
        v |= __shfl_xor_sync(0xffffffffu, v, 2);
        v |= __shfl_xor_sync(0xffffffffu, v, 4);
        if ((i & 7) == 0) selw[i >> 3] = v;
    }

    __shared__ double sacc[3];
    __shared__ int scnt[2];
    if (threadIdx.x < 3) sacc[threadIdx.x] = 0.0;
    if (threadIdx.x < 2) scnt[threadIdx.x] = 0;
    __syncthreads();
    int lane = threadIdx.x & 31;
    float ra = wredf(tA), rb = wredf(tB), rc = wredf(tC);
    int rp = wredi(pos), rn = wredi(neg);
    if (lane == 0) {
        atomicAdd(&sacc[0], (double)ra);
        atomicAdd(&sacc[1], (double)rb);
        atomicAdd(&sacc[2], (double)rc);
        atomicAdd(&scnt[0], rp);
        atomicAdd(&scnt[1], rn);
    }
    __syncthreads();
    if (threadIdx.x == 0) atomicAdd(&g.ta[cb],  sacc[0]);
    if (threadIdx.x == 1) atomicAdd(&g.tb_[cb], sacc[1]);
    if (threadIdx.x == 2) atomicAdd(&g.tc_[cb], sacc[2]);
    if (threadIdx.x == 3) atomicAdd(&g.pos[cb], scnt[0]);
    if (threadIdx.x == 4) atomicAdd(&g.negtot[cb], scnt[1]);
}

// ---------------------------------------------------------------------------
// kern_pass: one (cb, k) channel pair per blockIdx.y (80 slices).
// Pure 2-stream read + broadcast sel word. grid (40, 80) x 256: 10 trips.
// ---------------------------------------------------------------------------
__global__ void __launch_bounds__(256) kern_pass(
    const float* __restrict__ outp, const float* __restrict__ lab) {
    int slice = blockIdx.y;
    int cb = slice / NK, k = slice % NK;
    int c = cb >> 3, b = cb & 7;
    const float4* pv4 = (const float4*)outp + (size_t)(b * 12 + c * 6 + k) * HW4;
    const float4* tv4 = (const float4*)lab  + (size_t)(b * 12 + c * 6 + k) * HW4;
    const unsigned* selw = g.selw[cb];

    int base = blockIdx.x * 256 + threadIdx.x;   // stride 10240, 10 trips
    float A = 0.f, B = 0.f, C = 0.f;

#pragma unroll 5
    for (int it = 0; it < 10; it++) {
        int i = base + it * 10240;
        float4 p4 = pv4[i];
        float4 t4 = tv4[i];
        unsigned w = selw[i >> 3];
        unsigned nib = (w >> ((i & 7) * 4)) & 0xFu;
        float pv[4] = {p4.x, p4.y, p4.z, p4.w};
        float tv[4] = {t4.x, t4.y, t4.z, t4.w};
#pragma unroll
        for (int l = 0; l < 4; l++) {
            bool s = (nib >> l) & 1u;
            float p = s ? sigmoidf(pv[l]) : 0.0f;
            float t = s ? tv[l] : 0.0f;
            A = fmaf(p, t, A);
            B = fmaf(p, p, B);
            C = fmaf(t, t, C);
        }
    }

    __shared__ double sacc[3];
    if (threadIdx.x < 3) sacc[threadIdx.x] = 0.0;
    __syncthreads();
    int lane = threadIdx.x & 31;
    float ra = wredf(A), rb = wredf(B), rc = wredf(C);
    if (lane == 0) {
        atomicAdd(&sacc[0], (double)ra);
        atomicAdd(&sacc[1], (double)rb);
        atomicAdd(&sacc[2], (double)rc);
    }
    __syncthreads();
    if (threadIdx.x == 0) atomicAdd(&g.ka[cb][k], sacc[0]);
    if (threadIdx.x == 1) atomicAdd(&g.kb[cb][k], sacc[1]);
    if (threadIdx.x == 2) atomicAdd(&g.kc[cb][k], sacc[2]);
}

// ---------------------------------------------------------------------------
// slow_path: ONE launch, 16 blocks (one per cb), 1024 threads.
// Computes mode; mode 0 exits. mode 1: float-tm text sums. mode 2: exact
// 4-round 8-bit radix select in SMEM, then thr-masked text sums.
// Only runs real work when the data demands it (never on this distribution).
// ---------------------------------------------------------------------------
__global__ void __launch_bounds__(1024) slow_path(
    const float* __restrict__ outp, const float* __restrict__ lab,
    const float* __restrict__ tmask) {
    int cb = blockIdx.x;
    int tid = threadIdx.x;
    int pos = g.pos[cb], ntot = g.negtot[cb];
    int nn = min(pos * 3, ntot);
    int mode = (pos == 0 || nn == 0) ? 1 : (nn == ntot ? 0 : 2);
    if (tid == 0) g.mode[cb] = mode;
    if (mode == 0) return;

    int c = cb >> 3, b = cb & 7;
    const float4* tx = (const float4*)outp + (size_t)(b * 12 + c * 6 + 5) * HW4;
    const float4* gt = (const float4*)lab  + (size_t)(b * 12 + c * 6 + 5) * HW4;
    const float4* tm = (const float4*)tmask + (size_t)b * HW4;

    __shared__ int shist[256];
    __shared__ int sd, srank;
    __shared__ double swarp[32][3];

    float thr = 0.0f;
    if (mode == 2) {
        // exact rank-nn largest among neg scores, 8 bits per round
        unsigned prefix = 0;
        int rank = nn;
        for (int r = 0; r < 4; r++) {
            int shift = 24 - 8 * r;
            for (int j = tid; j < 256; j += 1024) shist[j] = 0;
            __syncthreads();
            for (int i = tid; i < HW4; i += 1024) {
                float4 s4 = tx[i], g4 = gt[i];
                float sv[4] = {s4.x, s4.y, s4.z, s4.w};
                float gv[4] = {g4.x, g4.y, g4.z, g4.w};
#pragma unroll
                for (int l = 0; l < 4; l++) {
                    if (gv[l] <= 0.5f) {
                        unsigned key = f2key(sv[l]);
                        if (r == 0 || (key >> (shift + 8)) == prefix)
                            atomicAdd(&shist[(key >> shift) & 0xFF], 1);
                    }
                }
            }
            __syncthreads();
            if (tid == 0) {
                int cum = 0, d = 0, rnew = rank;
                for (int j = 255; j >= 0; j--) {
                    cum += shist[j];
                    if (cum >= rank) { d = j; rnew = rank - (cum - shist[j]); break; }
                }
                sd = d; srank = rnew;
            }
            __syncthreads();
            prefix = (prefix << 8) | (unsigned)sd;
            rank = srank;
            __syncthreads();
        }
        thr = key2f(prefix);
        if (tid == 0) g.thr[cb] = thr;
    }

    // text dice sums with the applicable mask
    float A = 0.f, B = 0.f, C = 0.f;
    for (int i = tid; i < HW4; i += 1024) {
        float4 s4 = tx[i], g4 = gt[i], m4 = tm[i];
        float sv[4] = {s4.x, s4.y, s4.z, s4.w};
        float gv[4] = {g4.x, g4.y, g4.z, g4.w};
        float mv[4] = {m4.x, m4.y, m4.z, m4.w};
#pragma unroll
        for (int l = 0; l < 4; l++) {
            float m;
            if (mode == 1) m = mv[l];
            else m = (((sv[l] >= thr) || (gv[l] > 0.5f)) && (mv[l] > 0.5f)) ? 1.0f : 0.0f;
            float p = sigmoidf(sv[l]) * m;
            float t = gv[l] * m;
            A = fmaf(p, t, A);
            B = fmaf(p, p, B);
            C = fmaf(t, t, C);
        }
    }
    int lane = tid & 31, wid = tid >> 5;
    float ra = wredf(A), rb = wredf(B), rc = wredf(C);
    if (lane == 0) { swarp[wid][0] = ra; swarp[wid][1] = rb; swarp[wid][2] = rc; }
    __syncthreads();
    if (tid == 0) {
        double a = 0, bb = 0, cc = 0;
        for (int w = 0; w < 32; w++) { a += swarp[w][0]; bb += swarp[w][1]; cc += swarp[w][2]; }
        if (mode == 1) { g.taf[cb] = a; g.tbf[cb] = bb; g.tcf[cb] = cc; }
        else           { g.ta2[cb] = a; g.tb2[cb] = bb; g.tc2[cb] = cc; }
    }
}

// ---------------------------------------------------------------------------
// finalize: PARALLEL. 80 threads do the kernel-dice terms, 16 do the text
// terms — all global loads in flight simultaneously instead of one serial
// chain on thread 0 (which cost 63us in R5).
// ---------------------------------------------------------------------------
__global__ void __launch_bounds__(128) finalize(float* __restrict__ res) {
    int t = threadIdx.x;
    __shared__ float sdk[NCB * NK];   // kernel dice terms per (cb,k)
    __shared__ float slt[NCB];        // text dice terms per cb

    if (t < NCB * NK) {
        int cb = t / NK, k = t % NK;
        double a = g.ka[cb][k], b = g.kb[cb][k], c = g.kc[cb][k];
        sdk[t] = (float)(1.0 - 2.0 * a / (b + c + 2.0 * EPSV));
    }
    if (t >= 96 && t < 96 + NCB) {
        int cb = t - 96;
        int m = g.mode[cb];
        double A, B, C;
        if (m == 0)      { A = g.ta[cb];  B = g.tb_[cb]; C = g.tc_[cb]; }
        else if (m == 1) { A = g.taf[cb]; B = g.tbf[cb]; C = g.tcf[cb]; }
        else             { A = g.ta2[cb]; B = g.tb2[cb]; C = g.tc2[cb]; }
        slt[cb] = (float)(1.0 - 2.0 * A / (B + C + 2.0 * EPSV));
    }
    __syncthreads();
    if (t == 0) {
        float lt_sum = 0.f, lk_sum = 0.f;
        for (int cb = 0; cb < NCB; cb++) {
            lt_sum += slt[cb];
            float dks = 0.f;
#pragma unroll
            for (int k = 0; k < NK; k++) dks += sdk[cb * NK + k];
            lk_sum += dks * (1.0f / (float)NK);
        }
        lt_sum *= (1.0f / (float)NCB);
        lk_sum *= (1.0f / (float)NCB);
        res[0] = 0.7f * lt_sum + 0.3f * lk_sum;
        res[1] = lt_sum;
        res[2] = lk_sum;
    }
}

extern "C" void kernel_launch(void* const* d_in, const int* in_sizes, int n_in,
                              void* d_out, int out_size) {
    const float* outp = (const float*)d_in[0];
    const float* lab  = (const float*)d_in[1];
    const float* tm   = (const float*)d_in[2];
    float* res = (float*)d_out;

    void* gaddr = nullptr;
    cudaGetSymbolAddress(&gaddr, g);
    cudaMemsetAsync(gaddr, 0, offsetof(Scratch, selw));   // ~3.4 KB header

    dim3 gt(100, 16);
    text_pass<<<gt, 256>>>(outp, lab, tm);
    dim3 gk(40, 80);
    kern_pass<<<gk, 256>>>(outp, lab);
    slow_path<<<16, 1024>>>(outp, lab, tm);
    finalize<<<1, 128>>>(res);
}